// round 10
// baseline (speedup 1.0000x reference)
#include <cuda_runtime.h>
#include <cuda_bf16.h>
#include <math.h>
#include <stdint.h>

#define NN    8192
#define KK    32
#define NROWS 9
#define RAD3  768
#define NTH   256

// ---- scratch ----
__device__ float g_node[(size_t)NN * NROWS * 128];
__device__ __nv_bfloat16 g_w2h[768 * 64], g_w2l[768 * 64];
__device__ __nv_bfloat16 g_fch[256 * 768], g_fcl[256 * 768];

__device__ __forceinline__ void split_bf16(float v, __nv_bfloat16& hi, __nv_bfloat16& lo) {
    hi = __float2bfloat16(v);
    lo = __float2bfloat16(v - __bfloat162float(hi));
}

// ===================== K01: node projection + weight pre-split ===============
__global__ void k01(const float* __restrict__ node_in,
                    const float* __restrict__ dot_w,
                    const float* __restrict__ dot_b,
                    const float* __restrict__ w2,
                    const float* __restrict__ fcw) {
    // weight split: 24 elems per block (8192*24 = 196608 = 256*768)
    if (threadIdx.x < 24) {
        int i = blockIdx.x * 24 + threadIdx.x;
        if (i < 768 * 64) {
            __nv_bfloat16 h, l; split_bf16(w2[i], h, l);
            g_w2h[i] = h; g_w2l[i] = l;
        }
        __nv_bfloat16 h, l; split_bf16(fcw[i], h, l);
        g_fch[i] = h; g_fcl[i] = l;
    }
    __shared__ __align__(16) float sm[NROWS * 128];
    int n = blockIdx.x;
    const float* src = node_in + (size_t)n * NROWS * 128;
    for (int i = threadIdx.x; i < NROWS * 128; i += blockDim.x) sm[i] = src[i];
    __syncthreads();
    for (int idx = threadIdx.x; idx < NROWS * 128; idx += blockDim.x) {
        int m = idx >> 7;
        int d = idx & 127;
        int l = (m == 0) ? 0 : (m < 4 ? 1 : 2);
        const float4* w = reinterpret_cast<const float4*>(dot_w + (size_t)l * 128 * 128 + (size_t)d * 128);
        const float4* x = reinterpret_cast<const float4*>(sm + m * 128);
        float acc = (m == 0) ? dot_b[d] : 0.f;
#pragma unroll
        for (int c4 = 0; c4 < 32; c4++) {
            float4 wv = __ldg(&w[c4]);
            float4 xv = x[c4];
            acc += wv.x * xv.x + wv.y * xv.y + wv.z * xv.z + wv.w * xv.w;
        }
        g_node[(size_t)n * NROWS * 128 + idx] = acc;
    }
}

// ===================== helpers =====================
__device__ __forceinline__ uint32_t sptr(const void* p) {
    return (uint32_t)__cvta_generic_to_shared(p);
}
__device__ __forceinline__ void ldmx4(uint32_t addr, uint32_t& r0, uint32_t& r1,
                                      uint32_t& r2, uint32_t& r3) {
    asm volatile("ldmatrix.sync.aligned.m8n8.x4.shared.b16 {%0,%1,%2,%3}, [%4];"
                 : "=r"(r0), "=r"(r1), "=r"(r2), "=r"(r3) : "r"(addr));
}
__device__ __forceinline__ void mma16816(float* c, const uint32_t* a, const uint32_t* b) {
    asm volatile("mma.sync.aligned.m16n8k16.row.col.f32.bf16.bf16.f32 "
                 "{%0,%1,%2,%3}, {%4,%5,%6,%7}, {%8,%9}, {%0,%1,%2,%3};"
                 : "+f"(c[0]), "+f"(c[1]), "+f"(c[2]), "+f"(c[3])
                 : "r"(a[0]), "r"(a[1]), "r"(a[2]), "r"(a[3]), "r"(b[0]), "r"(b[1]));
}
__device__ __forceinline__ void cpa16(void* s, const void* g) {
    asm volatile("cp.async.cg.shared.global [%0], [%1], 16;" :: "r"(sptr(s)), "l"(g));
}
__device__ __forceinline__ void cpa_commit() { asm volatile("cp.async.commit_group;"); }
template<int N> __device__ __forceinline__ void cpa_wait() {
    asm volatile("cp.async.wait_group %0;" :: "n"(N));
}

// ===================== smem layout (bytes) =====================
#define OFF_Y    0          // 17408: x0 (32x132 f) | Y hi 8704 + lo 8704
#define OFF_H    17408      // 9216: h0s (32x68 f) | H hi 4608 + lo 4608
#define OFF_W2   26624      // 36864: w0s (64x132 f) | W2 hi 18432 + lo 18432
#define OFF_FCW  63488      // 40960: w1s/h1s | 2 x (hi 10240 + lo 10240)
#define FCWB     20480
#define OFF_NF   104448     // 4608
#define OFF_SH   109056     // 1536
#define OFF_IDX  110592     // 128
#define SMEM_B   110720

__device__ __forceinline__ void ln_silu_h0(float* hs, const float* __restrict__ g,
                                           const float* __restrict__ b, int tid) {
    int e = tid >> 3, p = tid & 7;
    float* row = hs + e * 68 + p * 8;
    float v[8];
    float s1 = 0.f, s2 = 0.f;
#pragma unroll
    for (int i = 0; i < 8; i++) { v[i] = row[i]; s1 += v[i]; s2 += v[i] * v[i]; }
    s1 += __shfl_xor_sync(0xffffffff, s1, 1);
    s2 += __shfl_xor_sync(0xffffffff, s2, 1);
    s1 += __shfl_xor_sync(0xffffffff, s1, 2);
    s2 += __shfl_xor_sync(0xffffffff, s2, 2);
    s1 += __shfl_xor_sync(0xffffffff, s1, 4);
    s2 += __shfl_xor_sync(0xffffffff, s2, 4);
    float mean = s1 * (1.f / 64.f);
    float var  = s2 * (1.f / 64.f) - mean * mean;
    float rs   = rsqrtf(var + 1e-5f);
#pragma unroll
    for (int i = 0; i < 8; i++) {
        float z = (v[i] - mean) * rs * __ldg(&g[p * 8 + i]) + __ldg(&b[p * 8 + i]);
        row[i] = z / (1.f + expf(-z));
    }
}

// FCW substage: 128n x 32k hi+lo (stride 40), one commit group
__device__ __forceinline__ void issue_fcw(char* smem, int fb, int b, int nsub, int ksub, int tid) {
    __nv_bfloat16* dh = (__nv_bfloat16*)(smem + OFF_FCW + fb * FCWB);
    __nv_bfloat16* dl = (__nv_bfloat16*)(smem + OFF_FCW + fb * FCWB + 10240);
#pragma unroll
    for (int j = 0; j < 2; j++) {
        int cid = tid + NTH * j;           // 0..511
        int nr = cid >> 2, kc = cid & 3;
        size_t src = (size_t)(nsub * 128 + nr) * RAD3 + b * 128 + ksub * 32 + kc * 8;
        cpa16(&dh[nr * 40 + kc * 8], g_fch + src);
        cpa16(&dl[nr * 40 + kc * 8], g_fcl + src);
    }
    cpa_commit();
}
// W2 chunk: 128j x 64k hi+lo (stride 72), one commit group
__device__ __forceinline__ void issue_w2(char* smem, int b, int tid) {
    __nv_bfloat16* dh = (__nv_bfloat16*)(smem + OFF_W2);
    __nv_bfloat16* dl = (__nv_bfloat16*)(smem + OFF_W2 + 18432);
#pragma unroll
    for (int j = 0; j < 4; j++) {
        int cid = tid + NTH * j;           // 0..1023
        int nr = cid >> 3, kc = cid & 7;
        size_t src = (size_t)(b * 128 + nr) * 64 + kc * 8;
        cpa16(&dh[nr * 72 + kc * 8], g_w2h + src);
        cpa16(&dl[nr * 72 + kc * 8], g_w2l + src);
    }
    cpa_commit();
}

// ===================== K2 fused: 32 edges (1 node) per block =================
__global__ void __launch_bounds__(NTH, 2) k2_fused(
    const float* __restrict__ x_edge, const float* __restrict__ edge_vec,
    const int* __restrict__ sp_idx,
    const float* __restrict__ w0, const float* __restrict__ b0,
    const float* __restrict__ w1, const float* __restrict__ b1,
    const float* __restrict__ b2,
    const float* __restrict__ g0, const float* __restrict__ bb0,
    const float* __restrict__ g1, const float* __restrict__ bb1,
    const float* __restrict__ fc_b,
    const float* __restrict__ ln_g, const float* __restrict__ ln_b,
    const float* __restrict__ alpha_dot, float* __restrict__ out)
{
    extern __shared__ __align__(16) char smem[];
    float* x0f  = (float*)(smem + OFF_Y);              // 32 x 132
    float* h0s  = (float*)(smem + OFF_H);              // 32 x 68
    float* w0s  = (float*)(smem + OFF_W2);             // 64 x 132
    float* w1s  = (float*)(smem + OFF_FCW);            // 64 x 68
    float* h1s  = (float*)(smem + OFF_FCW + FCWB);     // 32 x 68
    float* nfs  = (float*)(smem + OFF_NF);             // 1152
    float* shs  = (float*)(smem + OFF_SH);             // 32 x 12
    int*   idxs = (int*)(smem + OFF_IDX);

    __nv_bfloat16* Yh  = (__nv_bfloat16*)(smem + OFF_Y);          // 32 x 136
    __nv_bfloat16* Yl  = (__nv_bfloat16*)(smem + OFF_Y + 8704);
    __nv_bfloat16* Hhi = (__nv_bfloat16*)(smem + OFF_H);          // 32 x 72
    __nv_bfloat16* Hlo = (__nv_bfloat16*)(smem + OFF_H + 4608);
    __nv_bfloat16* W2h = (__nv_bfloat16*)(smem + OFF_W2);         // 128 x 72
    __nv_bfloat16* W2l = (__nv_bfloat16*)(smem + OFF_W2 + 18432);

    int tid = threadIdx.x;
    int n   = blockIdx.x;
    int eg0 = n * 32;

    // ---- stage inputs ----
    if (tid < 32) idxs[tid] = sp_idx[eg0 + tid];
    for (int i = tid; i < NROWS * 128; i += NTH)
        nfs[i] = g_node[(size_t)n * NROWS * 128 + i];
    for (int i = tid; i < 32 * 128; i += NTH) {
        int e = i >> 7, c = i & 127;
        x0f[e * 132 + c] = x_edge[(size_t)(eg0 + e) * 128 + c];
    }
    for (int i = tid; i < 64 * 128; i += NTH) {
        int o = i >> 7, c = i & 127;
        w0s[o * 132 + c] = __ldg(&w0[o * 128 + c]);
    }
    for (int i = tid; i < 64 * 64; i += NTH) {
        int o = i >> 6, c = i & 63;
        w1s[o * 68 + c] = __ldg(&w1[o * 64 + c]);
    }
    if (tid < 32) {
        const float* ev = edge_vec + (size_t)(eg0 + tid) * 3;
        float x = ev[0], y = ev[1], z = ev[2];
        float nrm = sqrtf(x * x + y * y + z * z);
        float inv = 1.f / fmaxf(nrm, 1e-12f);
        x *= inv; y *= inv; z *= inv;
        float* s = shs + tid * 12;
        const float C0 = 0.28209479177387814f;
        const float C1 = 0.4886025119029199f;
        const float C2 = 0.6307831305050401f;
        const float S3 = 1.7320508075688772f;
        s[0] = C0;
        s[1] = C1 * x; s[2] = C1 * y; s[3] = C1 * z;
        s[4] = C2 * S3 * x * z;
        s[5] = C2 * S3 * x * y;
        s[6] = C2 * (y * y - 0.5f * (x * x + z * z));
        s[7] = C2 * S3 * y * z;
        s[8] = C2 * 0.5f * S3 * (z * z - x * x);
    }
    __syncthreads();

    int tx = tid & 15, ty = tid >> 4;
    int o4 = tx * 4, e2 = ty * 2;

    // ---- rad0: 32e x 64o, k=128 (xs = x0f) ----
    {
        float a[2][4];
        float4 bv = *(const float4*)&b0[o4];
#pragma unroll
        for (int i = 0; i < 2; i++) { a[i][0]=bv.x; a[i][1]=bv.y; a[i][2]=bv.z; a[i][3]=bv.w; }
#pragma unroll 4
        for (int k4 = 0; k4 < 32; k4++) {
            float4 xv[2], wv[4];
#pragma unroll
            for (int i = 0; i < 2; i++) xv[i] = *(const float4*)&x0f[(e2 + i) * 132 + k4 * 4];
#pragma unroll
            for (int j = 0; j < 4; j++) wv[j] = *(const float4*)&w0s[(o4 + j) * 132 + k4 * 4];
#pragma unroll
            for (int i = 0; i < 2; i++)
#pragma unroll
                for (int j = 0; j < 4; j++)
                    a[i][j] += xv[i].x * wv[j].x + xv[i].y * wv[j].y +
                               xv[i].z * wv[j].z + xv[i].w * wv[j].w;
        }
#pragma unroll
        for (int i = 0; i < 2; i++)
            *(float4*)&h0s[(e2 + i) * 68 + o4] = make_float4(a[i][0], a[i][1], a[i][2], a[i][3]);
    }
    __syncthreads();               // w0s dead
    issue_w2(smem, 0, tid);        // pending: {W2(0)}
    ln_silu_h0(h0s, g0, bb0, tid);
    __syncthreads();

    // ---- rad1: 32e x 64o, k=64 ----
    {
        float a[2][4];
        float4 bv = *(const float4*)&b1[o4];
#pragma unroll
        for (int i = 0; i < 2; i++) { a[i][0]=bv.x; a[i][1]=bv.y; a[i][2]=bv.z; a[i][3]=bv.w; }
#pragma unroll 4
        for (int k4 = 0; k4 < 16; k4++) {
            float4 xv[2], wv[4];
#pragma unroll
            for (int i = 0; i < 2; i++) xv[i] = *(const float4*)&h0s[(e2 + i) * 68 + k4 * 4];
#pragma unroll
            for (int j = 0; j < 4; j++) wv[j] = *(const float4*)&w1s[(o4 + j) * 68 + k4 * 4];
#pragma unroll
            for (int i = 0; i < 2; i++)
#pragma unroll
                for (int j = 0; j < 4; j++)
                    a[i][j] += xv[i].x * wv[j].x + xv[i].y * wv[j].y +
                               xv[i].z * wv[j].z + xv[i].w * wv[j].w;
        }
#pragma unroll
        for (int i = 0; i < 2; i++)
            *(float4*)&h1s[(e2 + i) * 68 + o4] = make_float4(a[i][0], a[i][1], a[i][2], a[i][3]);
    }
    __syncthreads();               // rad1 done (w1s dead after this phase's reads)

    // ---- LN(h1) + SiLU + split -> H (h0s region) fused ----
    {
        int e = tid >> 3, p = tid & 7;
        const float* row = h1s + e * 68 + p * 8;
        float v[8];
        float s1 = 0.f, s2 = 0.f;
#pragma unroll
        for (int i = 0; i < 8; i++) { v[i] = row[i]; s1 += v[i]; s2 += v[i] * v[i]; }
        s1 += __shfl_xor_sync(0xffffffff, s1, 1);
        s2 += __shfl_xor_sync(0xffffffff, s2, 1);
        s1 += __shfl_xor_sync(0xffffffff, s1, 2);
        s2 += __shfl_xor_sync(0xffffffff, s2, 2);
        s1 += __shfl_xor_sync(0xffffffff, s1, 4);
        s2 += __shfl_xor_sync(0xffffffff, s2, 4);
        float mean = s1 * (1.f / 64.f);
        float var  = s2 * (1.f / 64.f) - mean * mean;
        float rs   = rsqrtf(var + 1e-5f);
        __syncthreads();           // h0s reads (rad1) fully done before H overwrite
#pragma unroll
        for (int i = 0; i < 8; i++) {
            float z = (v[i] - mean) * rs * __ldg(&g1[p * 8 + i]) + __ldg(&bb1[p * 8 + i]);
            float sil = z / (1.f + expf(-z));
            __nv_bfloat16 hi, lo;
            split_bf16(sil, hi, lo);
            Hhi[e * 72 + p * 8 + i] = hi;
            Hlo[e * 72 + p * 8 + i] = lo;
        }
    }
    __syncthreads();               // h1s (FCW buf1) dead
    issue_fcw(smem, 0, 0, 0, 0, tid);   // s0: pending {W2, s0}
    issue_fcw(smem, 1, 0, 0, 1, tid);   // s1: pending {W2, s0, s1}

    // ---- warp roles ----
    int lane = tid & 31, warp = tid >> 5;
    int eg2 = warp & 1, jg = warp >> 1;   // w2-mma: 16e x 32j
    int egF = warp >> 2, wn = warp & 3;   // FC: 16e x 32n per nsub
    int g = lane >> 3, r = lane & 7;
    int h_row = r + ((g & 1) << 3);
    int h_col = (g >> 1) << 3;
    int b_n   = r + ((g >> 1) << 3);
    int b_k   = (g & 1) << 3;
    int e_lo = lane >> 2, q = lane & 3;

    float acc[2][4][4];            // [nsub][np*2+n8][frag]
#pragma unroll
    for (int a0 = 0; a0 < 2; a0++)
#pragma unroll
        for (int a1 = 0; a1 < 4; a1++)
#pragma unroll
            for (int a2 = 0; a2 < 4; a2++) acc[a0][a1][a2] = 0.f;

    // ---- 6 chunks of 128 j/k ----
    for (int b = 0; b < 6; b++) {
        int bn = (b < 5) ? b + 1 : 0;

        // x0 gather (32 x 128) -> x0f (Y region; previous Y fully consumed)
        for (int i = tid; i < 32 * 128; i += NTH) {
            int e = i >> 7, d = i & 127;
            const float* s = shs + e * 12;
            const float* src = (b & 1) ? g_node + (size_t)idxs[e] * (NROWS * 128) : nfs;
            float x0;
            if      (b < 2) x0 = s[0] * src[d];
            else if (b < 4) x0 = s[1] * src[128 + d] + s[2] * src[256 + d] + s[3] * src[384 + d];
            else            x0 = s[4] * src[512 + d] + s[5] * src[640 + d] + s[6] * src[768 + d]
                               + s[7] * src[896 + d] + s[8] * src[1024 + d];
            x0f[e * 132 + d] = x0;
        }
        cpa_wait<2>();             // W2(b) resident (s0,s1 may pend)
        __syncthreads();

        // w2-mma: warp tile 16e x 32j
        float2 x0v[2][2][2];
#pragma unroll
        for (int np = 0; np < 2; np++)
#pragma unroll
            for (int n8 = 0; n8 < 2; n8++)
#pragma unroll
                for (int hf = 0; hf < 2; hf++) {
                    int e = eg2 * 16 + e_lo + hf * 8;
                    int jl = jg * 32 + np * 16 + n8 * 8 + 2 * q;
                    x0v[np][n8][hf] = *(const float2*)&x0f[e * 132 + jl];
                }
        float acc2[2][2][4];
#pragma unroll
        for (int np = 0; np < 2; np++)
#pragma unroll
            for (int n8 = 0; n8 < 2; n8++)
#pragma unroll
                for (int c = 0; c < 4; c++) acc2[np][n8][c] = 0.f;
#pragma unroll
        for (int kk = 0; kk < 4; kk++) {
            uint32_t ah[4], al[4];
            ldmx4(sptr(&Hhi[(eg2 * 16 + h_row) * 72 + kk * 16 + h_col]), ah[0], ah[1], ah[2], ah[3]);
            ldmx4(sptr(&Hlo[(eg2 * 16 + h_row) * 72 + kk * 16 + h_col]), al[0], al[1], al[2], al[3]);
#pragma unroll
            for (int np = 0; np < 2; np++) {
                uint32_t bh[4], bl[4];
                ldmx4(sptr(&W2h[(jg * 32 + np * 16 + b_n) * 72 + kk * 16 + b_k]), bh[0], bh[1], bh[2], bh[3]);
                ldmx4(sptr(&W2l[(jg * 32 + np * 16 + b_n) * 72 + kk * 16 + b_k]), bl[0], bl[1], bl[2], bl[3]);
#pragma unroll
                for (int n8 = 0; n8 < 2; n8++) {
                    float* c = acc2[np][n8];
                    mma16816(c, ah, &bh[n8 * 2]);
                    mma16816(c, al, &bh[n8 * 2]);
                    mma16816(c, ah, &bl[n8 * 2]);
                }
            }
        }
        __syncthreads();           // all x0 reads done before Y overwrite

        // y = x0*(m0+b2) -> Y hi/lo
#pragma unroll
        for (int np = 0; np < 2; np++) {
#pragma unroll
            for (int n8 = 0; n8 < 2; n8++) {
                int jl = jg * 32 + np * 16 + n8 * 8 + 2 * q;
                int jgl = b * 128 + jl;
                float b2v0 = __ldg(&b2[jgl]);
                float b2v1 = __ldg(&b2[jgl + 1]);
#pragma unroll
                for (int hf = 0; hf < 2; hf++) {
                    int e = eg2 * 16 + e_lo + hf * 8;
                    float y0 = x0v[np][n8][hf].x * (acc2[np][n8][hf * 2]     + b2v0);
                    float y1 = x0v[np][n8][hf].y * (acc2[np][n8][hf * 2 + 1] + b2v1);
                    __nv_bfloat16 yh0, yl0, yh1, yl1;
                    split_bf16(y0, yh0, yl0);
                    split_bf16(y1, yh1, yl1);
                    *reinterpret_cast<__nv_bfloat162*>(&Yh[e * 136 + jl]) = __nv_bfloat162(yh0, yh1);
                    *reinterpret_cast<__nv_bfloat162*>(&Yl[e * 136 + jl]) = __nv_bfloat162(yl0, yl1);
                }
            }
        }
        __syncthreads();           // Y visible

        // FC: 8 substages (nsub = s>>2, ksub = s&3), buffer fb = s&1
#pragma unroll
        for (int s = 0; s < 8; s++) {
            int nsub = s >> 2, ksub = s & 3, fb = s & 1;
            cpa_wait<1>();         // substage s resident
            __syncthreads();
            const __nv_bfloat16* Fh = (const __nv_bfloat16*)(smem + OFF_FCW + fb * FCWB);
            const __nv_bfloat16* Fl = (const __nv_bfloat16*)(smem + OFF_FCW + fb * FCWB + 10240);
#pragma unroll
            for (int kk = 0; kk < 2; kk++) {
                uint32_t ah[4], al[4];
                ldmx4(sptr(&Yh[(egF * 16 + h_row) * 136 + ksub * 32 + kk * 16 + h_col]), ah[0], ah[1], ah[2], ah[3]);
                ldmx4(sptr(&Yl[(egF * 16 + h_row) * 136 + ksub * 32 + kk * 16 + h_col]), al[0], al[1], al[2], al[3]);
#pragma unroll
                for (int np = 0; np < 2; np++) {
                    uint32_t bh[4], bl[4];
                    ldmx4(sptr(&Fh[(wn * 32 + np * 16 + b_n) * 40 + kk * 16 + b_k]), bh[0], bh[1], bh[2], bh[3]);
                    ldmx4(sptr(&Fl[(wn * 32 + np * 16 + b_n) * 40 + kk * 16 + b_k]), bl[0], bl[1], bl[2], bl[3]);
#pragma unroll
                    for (int n8 = 0; n8 < 2; n8++) {
                        float* c = acc[nsub][np * 2 + n8];
                        mma16816(c, ah, &bh[n8 * 2]);
                        mma16816(c, al, &bh[n8 * 2]);
                        mma16816(c, ah, &bl[n8 * 2]);
                    }
                }
            }
            __syncthreads();       // buffer fb consumed by all warps
            if (s < 6)       issue_fcw(smem, fb, b, (s + 2) >> 2, (s + 2) & 3, tid);
            else if (s == 6) issue_w2(smem, bn, tid);
            else { issue_fcw(smem, 0, bn, 0, 0, tid); issue_fcw(smem, 1, bn, 0, 1, tid); }
        }
    }
    cpa_wait<0>();

    // ---- epilogue: warp (egF, wn): rows egF*16.., heads nsub*4+wn ----
#pragma unroll
    for (int nsub = 0; nsub < 2; nsub++) {
        int hg = nsub * 4 + wn;
#pragma unroll
        for (int half8 = 0; half8 < 2; half8++) {
            int erow = eg0 + egF * 16 + e_lo + half8 * 8;
            float v[8];
#pragma unroll
            for (int np = 0; np < 2; np++)
#pragma unroll
                for (int n8 = 0; n8 < 2; n8++)
#pragma unroll
                    for (int c = 0; c < 2; c++) {
                        int d  = np * 16 + n8 * 8 + 2 * q + c;
                        int ng = nsub * 128 + wn * 32 + d;
                        v[np * 4 + n8 * 2 + c] = acc[nsub][np * 2 + n8][half8 * 2 + c] + __ldg(&fc_b[ng]);
                    }
            float s1 = 0.f, s2 = 0.f;
#pragma unroll
            for (int j = 0; j < 8; j++) { s1 += v[j]; s2 += v[j] * v[j]; }
            s1 += __shfl_xor_sync(0xffffffff, s1, 1);
            s2 += __shfl_xor_sync(0xffffffff, s2, 1);
            s1 += __shfl_xor_sync(0xffffffff, s1, 2);
            s2 += __shfl_xor_sync(0xffffffff, s2, 2);
            float mean = s1 * (1.f / 32.f);
            float var  = s2 * (1.f / 32.f) - mean * mean;
            float rs   = rsqrtf(var + 1e-5f);
            float p = 0.f;
#pragma unroll
            for (int j = 0; j < 8; j++) {
                int np = j >> 2, n8 = (j >> 1) & 1, c = j & 1;
                int d = np * 16 + n8 * 8 + 2 * q + c;
                float z = (v[j] - mean) * rs * __ldg(&ln_g[d]) + __ldg(&ln_b[d]);
                float sg = 1.f / (1.f + expf(-z));
                float slr = 0.6f * z + 0.4f * z * (2.f * sg - 1.f);
                p += slr * __ldg(&alpha_dot[hg * 32 + d]);
            }
            p += __shfl_xor_sync(0xffffffff, p, 1);
            p += __shfl_xor_sync(0xffffffff, p, 2);
            if (q == 0)
                out[(size_t)erow * 8 + hg] = p;
        }
    }
}

// ===================== launch =====================
extern "C" void kernel_launch(void* const* d_in, const int* in_sizes, int n_in,
                              void* d_out, int out_size) {
    const float* x_edge   = (const float*)d_in[0];
    const float* node_in  = (const float*)d_in[1];
    const float* edge_vec = (const float*)d_in[2];
    const int*   sp       = (const int*)d_in[3];
    const float* dot_w    = (const float*)d_in[4];
    const float* dot_b    = (const float*)d_in[5];
    const float* w0  = (const float*)d_in[6];
    const float* b0  = (const float*)d_in[7];
    const float* w1  = (const float*)d_in[8];
    const float* b1  = (const float*)d_in[9];
    const float* w2  = (const float*)d_in[10];
    const float* b2  = (const float*)d_in[11];
    const float* g0  = (const float*)d_in[12];
    const float* bb0 = (const float*)d_in[13];
    const float* g1  = (const float*)d_in[14];
    const float* bb1 = (const float*)d_in[15];
    const float* fcw = (const float*)d_in[16];
    const float* fcb = (const float*)d_in[17];
    const float* lng = (const float*)d_in[18];
    const float* lnb = (const float*)d_in[19];
    const float* ad  = (const float*)d_in[20];
    float* out = (float*)d_out;

    k01<<<NN, 256>>>(node_in, dot_w, dot_b, w2, fcw);

    cudaFuncSetAttribute(k2_fused, cudaFuncAttributeMaxDynamicSharedMemorySize, SMEM_B);
    k2_fused<<<NN, NTH, SMEM_B>>>(x_edge, edge_vec, sp,
                                  w0, b0, w1, b1, b2, g0, bb0, g1, bb1,
                                  fcb, lng, lnb, ad, out);
}